// round 1
// baseline (speedup 1.0000x reference)
#include <cuda_runtime.h>
#include <math.h>

#define NL 128   // L lobes
#define NS 8     // samples per lobe
#define NH 16    // hidden units

// Per-l precomputed tables (written by setup_kernel, read by main_kernel)
__device__ float gA [NL * NH];   // sp * (U . M_j)
__device__ float gB [NL * NH];   // sp * (V . M_j)
__device__ float gC0[NL * NH];   // -cp * (l . M_j)
__device__ float gSU[NL * 3];    // sp * U
__device__ float gSV[NL * 3];    // sp * V
__device__ float gCL[NL * 3];    // cp * l
__device__ float gWt[NL];        // exp(sharp * (cp*|l|^2 - 1))

__global__ void setup_kernel(const float* __restrict__ root_rot,
                             const float* __restrict__ lobes,
                             const float* __restrict__ lambdas,
                             const float* __restrict__ W1)
{
    __shared__ float sM[3 * NH];   // M = R @ W1[3:6]  (M[d][j])
    int t = threadIdx.x;
    if (t < 3 * NH) {
        int d = t >> 4, j = t & 15;
        sM[t] = root_rot[d * 3 + 0] * W1[(3 + 0) * NH + j]
              + root_rot[d * 3 + 1] * W1[(3 + 1) * NH + j]
              + root_rot[d * 3 + 2] * W1[(3 + 2) * NH + j];
    }
    __syncthreads();

    int l = t;  // 128 threads, one per lobe
    float lx = lobes[3 * l + 0], ly = lobes[3 * l + 1], lz = lobes[3 * l + 2];
    float inv = 1.0f / (sqrtf(lx * lx + ly * ly + lz * lz) + 1e-6f);
    lx *= inv; ly *= inv; lz *= inv;

    // U = normalize(cross(z, l)) = normalize((-ly, lx, 0))
    float ux = -ly, uy = lx, uz = 0.0f;
    float un = 1.0f / (sqrtf(ux * ux + uy * uy) + 1e-6f);
    ux *= un; uy *= un;

    // V = normalize(cross(l, U))
    float vx = ly * uz - lz * uy;
    float vy = lz * ux - lx * uz;
    float vz = lx * uy - ly * ux;
    float vn = 1.0f / (sqrtf(vx * vx + vy * vy + vz * vz) + 1e-6f);
    vx *= vn; vy *= vn; vz *= vn;

    float sharp = lambdas[l];
    float rphi = acosf(1.0f - 1.0f / sharp);
    rphi = fminf(rphi, 1.0471975511965976f);  // pi/3
    float sp = sinf(rphi), cp = cosf(rphi);

    #pragma unroll
    for (int j = 0; j < NH; j++) {
        float mx = sM[j], my = sM[NH + j], mz = sM[2 * NH + j];
        gA [l * NH + j] = sp * (ux * mx + uy * my + uz * mz);
        gB [l * NH + j] = sp * (vx * mx + vy * my + vz * mz);
        gC0[l * NH + j] = -cp * (lx * mx + ly * my + lz * mz);
    }
    gSU[3 * l + 0] = sp * ux; gSU[3 * l + 1] = sp * uy; gSU[3 * l + 2] = sp * uz;
    gSV[3 * l + 0] = sp * vx; gSV[3 * l + 1] = sp * vy; gSV[3 * l + 2] = sp * vz;
    gCL[3 * l + 0] = cp * lx; gCL[3 * l + 1] = cp * ly; gCL[3 * l + 2] = cp * lz;

    float ll2 = lx * lx + ly * ly + lz * lz;
    gWt[l] = __expf(sharp * (cp * ll2 - 1.0f));
}

__global__ __launch_bounds__(NL) void main_kernel(
    const float* __restrict__ points,
    const float* __restrict__ normals,
    const float* __restrict__ rthr,
    const float* __restrict__ W1,
    const float* __restrict__ b1,
    const float* __restrict__ W2,
    const float* __restrict__ b2,
    float* __restrict__ out)
{
    int n = blockIdx.x;
    int l = threadIdx.x;

    __shared__ float spb[NH];
    __shared__ float snrm[3];
    if (l < NH) {
        float px = points[3 * n + 0], py = points[3 * n + 1], pz = points[3 * n + 2];
        spb[l] = fmaf(px, W1[l], fmaf(py, W1[NH + l], fmaf(pz, W1[2 * NH + l], b1[l])));
    }
    if (l >= 32 && l < 35) snrm[l - 32] = normals[3 * n + (l - 32)];
    __syncthreads();

    float nx = snrm[0], ny = snrm[1], nz = snrm[2];

    float A[NH], B[NH], C[NH], w2[NH];
    #pragma unroll
    for (int j = 0; j < NH; j++) {
        A[j]  = gA [l * NH + j];
        B[j]  = gB [l * NH + j];
        C[j]  = gC0[l * NH + j] + spb[j];
        w2[j] = W2[j];
    }
    float nU = gSU[3 * l] * nx + gSU[3 * l + 1] * ny + gSU[3 * l + 2] * nz;
    float nV = gSV[3 * l] * nx + gSV[3 * l + 1] * ny + gSV[3 * l + 2] * nz;
    float nC = gCL[3 * l] * nx + gCL[3 * l + 1] * ny + gCL[3 * l + 2] * nz;
    float bb2 = b2[0];

    const float4* rp = (const float4*)(rthr + (((size_t)n * NL + l) * NS));
    float4 ra = rp[0], rb = rp[1];
    float rr[NS] = {ra.x, ra.y, ra.z, ra.w, rb.x, rb.y, rb.z, rb.w};

    float vsum = 0.0f;
    #pragma unroll
    for (int s = 0; s < NS; s++) {
        // theta = 2*pi*(r + s)/8  ->  sin/cos(pi * u), u = (r+s)/4
        float u = 0.25f * (rr[s] + (float)s);
        float st, ct;
        sincospif(u, &st, &ct);

        float acc = bb2;
        #pragma unroll
        for (int j = 0; j < NH; j++) {
            float h = fmaf(-ct, A[j], fmaf(-st, B[j], C[j]));
            h = fmaxf(h, 0.0f);
            acc = fmaf(h, w2[j], acc);
        }
        float pred = 1.0f / (1.0f + __expf(-acc));
        float cd = fmaf(ct, nU, fmaf(st, nV, nC));
        vsum += (cd > 1e-6f) ? pred : 0.0f;
    }

    float w = gWt[l];
    out[(size_t)n * NL + l] = w * vsum / (8.0f * w + 1e-6f);
}

extern "C" void kernel_launch(void* const* d_in, const int* in_sizes, int n_in,
                              void* d_out, int out_size)
{
    const float* points   = (const float*)d_in[0];
    const float* normals  = (const float*)d_in[1];
    const float* root_rot = (const float*)d_in[2];
    const float* lobes    = (const float*)d_in[3];
    const float* lambdas  = (const float*)d_in[4];
    const float* rthr     = (const float*)d_in[5];
    const float* W1       = (const float*)d_in[6];
    const float* b1       = (const float*)d_in[7];
    const float* W2       = (const float*)d_in[8];
    const float* b2       = (const float*)d_in[9];
    float* out = (float*)d_out;

    int N = in_sizes[0] / 3;

    setup_kernel<<<1, NL>>>(root_rot, lobes, lambdas, W1);
    main_kernel<<<N, NL>>>(points, normals, rthr, W1, b1, W2, b2, out);
}

// round 2
// speedup vs baseline: 2.3488x; 2.3488x over previous
#include <cuda_runtime.h>
#include <math.h>

#define NL 128   // L lobes
#define NS 8     // samples per lobe
#define NH 16    // hidden units

// Per-l precomputed tables, LANE-MAJOR ([j][l] / [d][l]) for coalesced loads
__device__ float gA [NH * NL];   // sp * (U . M_j)           -> gA [j*NL + l]
__device__ float gB [NH * NL];   // sp * (V . M_j)           -> gB [j*NL + l]
__device__ float gC0[NH * NL];   // -cp * (l . M_j)          -> gC0[j*NL + l]
__device__ float gSU[3 * NL];    // sp * U                   -> gSU[d*NL + l]
__device__ float gSV[3 * NL];    // sp * V
__device__ float gCL[3 * NL];    // cp * l
__device__ float gWt[NL];        // exp(sharp * (cp*|l|^2 - 1))

__global__ void setup_kernel(const float* __restrict__ root_rot,
                             const float* __restrict__ lobes,
                             const float* __restrict__ lambdas,
                             const float* __restrict__ W1)
{
    __shared__ float sM[3 * NH];   // M = R @ W1[3:6]  (M[d][j])
    int t = threadIdx.x;
    if (t < 3 * NH) {
        int d = t >> 4, j = t & 15;
        sM[t] = root_rot[d * 3 + 0] * W1[(3 + 0) * NH + j]
              + root_rot[d * 3 + 1] * W1[(3 + 1) * NH + j]
              + root_rot[d * 3 + 2] * W1[(3 + 2) * NH + j];
    }
    __syncthreads();

    int l = t;  // 128 threads, one per lobe
    float lx = lobes[3 * l + 0], ly = lobes[3 * l + 1], lz = lobes[3 * l + 2];
    float inv = 1.0f / (sqrtf(lx * lx + ly * ly + lz * lz) + 1e-6f);
    lx *= inv; ly *= inv; lz *= inv;

    // U = normalize(cross(z, l)) = normalize((-ly, lx, 0))
    float ux = -ly, uy = lx, uz = 0.0f;
    float un = 1.0f / (sqrtf(ux * ux + uy * uy) + 1e-6f);
    ux *= un; uy *= un;

    // V = normalize(cross(l, U))
    float vx = ly * uz - lz * uy;
    float vy = lz * ux - lx * uz;
    float vz = lx * uy - ly * ux;
    float vn = 1.0f / (sqrtf(vx * vx + vy * vy + vz * vz) + 1e-6f);
    vx *= vn; vy *= vn; vz *= vn;

    float sharp = lambdas[l];
    float rphi = acosf(1.0f - 1.0f / sharp);
    rphi = fminf(rphi, 1.0471975511965976f);  // pi/3
    float sp = sinf(rphi), cp = cosf(rphi);

    #pragma unroll
    for (int j = 0; j < NH; j++) {
        float mx = sM[j], my = sM[NH + j], mz = sM[2 * NH + j];
        gA [j * NL + l] = sp * (ux * mx + uy * my + uz * mz);
        gB [j * NL + l] = sp * (vx * mx + vy * my + vz * mz);
        gC0[j * NL + l] = -cp * (lx * mx + ly * my + lz * mz);
    }
    gSU[0 * NL + l] = sp * ux; gSU[1 * NL + l] = sp * uy; gSU[2 * NL + l] = sp * uz;
    gSV[0 * NL + l] = sp * vx; gSV[1 * NL + l] = sp * vy; gSV[2 * NL + l] = sp * vz;
    gCL[0 * NL + l] = cp * lx; gCL[1 * NL + l] = cp * ly; gCL[2 * NL + l] = cp * lz;

    float ll2 = lx * lx + ly * ly + lz * lz;
    gWt[l] = __expf(sharp * (cp * ll2 - 1.0f));
}

__global__ __launch_bounds__(NL) void main_kernel(
    const float* __restrict__ points,
    const float* __restrict__ normals,
    const float* __restrict__ rthr,
    const float* __restrict__ W1,
    const float* __restrict__ b1,
    const float* __restrict__ W2,
    const float* __restrict__ b2,
    float* __restrict__ out)
{
    int n = blockIdx.x;
    int l = threadIdx.x;

    __shared__ float spb[NH];   // per-point bias: p @ W1[:3] + b1
    __shared__ float sw2[NH];
    __shared__ float snrm[3];
    if (l < NH) {
        float px = points[3 * n + 0], py = points[3 * n + 1], pz = points[3 * n + 2];
        spb[l] = fmaf(px, W1[l], fmaf(py, W1[NH + l], fmaf(pz, W1[2 * NH + l], b1[l])));
        sw2[l] = W2[l];
    }
    if (l >= 32 && l < 35) snrm[l - 32] = normals[3 * n + (l - 32)];
    __syncthreads();

    float nx = snrm[0], ny = snrm[1], nz = snrm[2];
    float nU = fmaf(gSU[l], nx, fmaf(gSU[NL + l], ny, gSU[2 * NL + l] * nz));
    float nV = fmaf(gSV[l], nx, fmaf(gSV[NL + l], ny, gSV[2 * NL + l] * nz));
    float nC = fmaf(gCL[l], nx, fmaf(gCL[NL + l], ny, gCL[2 * NL + l] * nz));
    float bb2 = b2[0];

    // Per-sample trig (16 live regs across the j-loop)
    const float4* rp = (const float4*)(rthr + (((size_t)n * NL + l) * NS));
    float4 ra = rp[0], rb = rp[1];
    float rr[NS] = {ra.x, ra.y, ra.z, ra.w, rb.x, rb.y, rb.z, rb.w};

    float st[NS], ct[NS], acc[NS];
    #pragma unroll
    for (int s = 0; s < NS; s++) {
        // theta = 2*pi*(r + s)/8  ->  sin/cos(pi * u), u = (r+s)/4
        float u = 0.25f * (rr[s] + (float)s);
        sincospif(u, &st[s], &ct[s]);
        acc[s] = bb2;
    }

    // j outer (stream tables, coalesced), s inner (8 accumulators)
    #pragma unroll
    for (int j = 0; j < NH; j++) {
        float Aj  = gA [j * NL + l];
        float Bj  = gB [j * NL + l];
        float Cj  = gC0[j * NL + l] + spb[j];
        float w2j = sw2[j];
        #pragma unroll
        for (int s = 0; s < NS; s++) {
            float h = fmaf(-ct[s], Aj, fmaf(-st[s], Bj, Cj));
            h = fmaxf(h, 0.0f);
            acc[s] = fmaf(h, w2j, acc[s]);
        }
    }

    float vsum = 0.0f;
    #pragma unroll
    for (int s = 0; s < NS; s++) {
        float pred = 1.0f / (1.0f + __expf(-acc[s]));
        float cd = fmaf(ct[s], nU, fmaf(st[s], nV, nC));
        vsum += (cd > 1e-6f) ? pred : 0.0f;
    }

    float w = gWt[l];
    out[(size_t)n * NL + l] = w * vsum / (8.0f * w + 1e-6f);
}

extern "C" void kernel_launch(void* const* d_in, const int* in_sizes, int n_in,
                              void* d_out, int out_size)
{
    const float* points   = (const float*)d_in[0];
    const float* normals  = (const float*)d_in[1];
    const float* root_rot = (const float*)d_in[2];
    const float* lobes    = (const float*)d_in[3];
    const float* lambdas  = (const float*)d_in[4];
    const float* rthr     = (const float*)d_in[5];
    const float* W1       = (const float*)d_in[6];
    const float* b1       = (const float*)d_in[7];
    const float* W2       = (const float*)d_in[8];
    const float* b2       = (const float*)d_in[9];
    float* out = (float*)d_out;

    int N = in_sizes[0] / 3;

    setup_kernel<<<1, NL>>>(root_rot, lobes, lambdas, W1);
    main_kernel<<<N, NL>>>(points, normals, rthr, W1, b1, W2, b2, out);
}

// round 3
// speedup vs baseline: 2.6516x; 1.1289x over previous
#include <cuda_runtime.h>
#include <math.h>

#define NL 128   // L lobes
#define NS 8     // samples per lobe
#define NH 16    // hidden units

// Per-l precomputed tables, LANE-MAJOR ([j][l] / [d][l]) for coalesced loads
__device__ float gA [NH * NL];   // sp * (U . M_j)           -> gA [j*NL + l]
__device__ float gB [NH * NL];   // sp * (V . M_j)           -> gB [j*NL + l]
__device__ float gC0[NH * NL];   // -cp * (l . M_j)          -> gC0[j*NL + l]
__device__ float gSU[3 * NL];    // sp * U                   -> gSU[d*NL + l]
__device__ float gSV[3 * NL];    // sp * V
__device__ float gCL[3 * NL];    // cp * l
__device__ float gWt[NL];        // exp(sharp * (cp*|l|^2 - 1))

__global__ void setup_kernel(const float* __restrict__ root_rot,
                             const float* __restrict__ lobes,
                             const float* __restrict__ lambdas,
                             const float* __restrict__ W1)
{
    __shared__ float sM[3 * NH];   // M = R @ W1[3:6]  (M[d][j])
    int t = threadIdx.x;
    if (t < 3 * NH) {
        int d = t >> 4, j = t & 15;
        sM[t] = root_rot[d * 3 + 0] * W1[(3 + 0) * NH + j]
              + root_rot[d * 3 + 1] * W1[(3 + 1) * NH + j]
              + root_rot[d * 3 + 2] * W1[(3 + 2) * NH + j];
    }
    __syncthreads();

    int l = t;  // 128 threads, one per lobe
    float lx = lobes[3 * l + 0], ly = lobes[3 * l + 1], lz = lobes[3 * l + 2];
    float inv = 1.0f / (sqrtf(lx * lx + ly * ly + lz * lz) + 1e-6f);
    lx *= inv; ly *= inv; lz *= inv;

    // U = normalize(cross(z, l)) = normalize((-ly, lx, 0))
    float ux = -ly, uy = lx, uz = 0.0f;
    float un = 1.0f / (sqrtf(ux * ux + uy * uy) + 1e-6f);
    ux *= un; uy *= un;

    // V = normalize(cross(l, U))
    float vx = ly * uz - lz * uy;
    float vy = lz * ux - lx * uz;
    float vz = lx * uy - ly * ux;
    float vn = 1.0f / (sqrtf(vx * vx + vy * vy + vz * vz) + 1e-6f);
    vx *= vn; vy *= vn; vz *= vn;

    float sharp = lambdas[l];
    float rphi = acosf(1.0f - 1.0f / sharp);
    rphi = fminf(rphi, 1.0471975511965976f);  // pi/3
    float sp = sinf(rphi), cp = cosf(rphi);

    #pragma unroll
    for (int j = 0; j < NH; j++) {
        float mx = sM[j], my = sM[NH + j], mz = sM[2 * NH + j];
        gA [j * NL + l] = sp * (ux * mx + uy * my + uz * mz);
        gB [j * NL + l] = sp * (vx * mx + vy * my + vz * mz);
        gC0[j * NL + l] = -cp * (lx * mx + ly * my + lz * mz);
    }
    gSU[0 * NL + l] = sp * ux; gSU[1 * NL + l] = sp * uy; gSU[2 * NL + l] = sp * uz;
    gSV[0 * NL + l] = sp * vx; gSV[1 * NL + l] = sp * vy; gSV[2 * NL + l] = sp * vz;
    gCL[0 * NL + l] = cp * lx; gCL[1 * NL + l] = cp * ly; gCL[2 * NL + l] = cp * lz;

    float ll2 = lx * lx + ly * ly + lz * lz;
    gWt[l] = __expf(sharp * (cp * ll2 - 1.0f));
}

// sin/cos of phi = (pi/4)*r for r in [0,1) — no range reduction needed.
// Minimax polys on [-pi/4, pi/4], abs err ~1e-9.
__device__ __forceinline__ void sincos_q(float r, float& sp, float& cp)
{
    float phi = 0.7853981633974483f * r;
    float x2  = phi * phi;
    float ps = fmaf(x2, -1.9515295891e-4f, 8.3321608736e-3f);
    ps       = fmaf(x2, ps, -1.6666654611e-1f);
    sp       = fmaf(phi * x2, ps, phi);
    float pc = fmaf(x2, 2.443315711809948e-5f, -1.388731625493765e-3f);
    pc       = fmaf(x2, pc, 4.166664568298827e-2f);
    pc       = fmaf(x2, pc, -0.5f);
    cp       = fmaf(x2, pc, 1.0f);
}

__global__ __launch_bounds__(NL) void main_kernel(
    const float* __restrict__ points,
    const float* __restrict__ normals,
    const float* __restrict__ rthr,
    const float* __restrict__ W1,
    const float* __restrict__ b1,
    const float* __restrict__ W2,
    const float* __restrict__ b2,
    float* __restrict__ out)
{
    int n = blockIdx.x;
    int l = threadIdx.x;

    __shared__ float spb[NH];   // per-point bias: p @ W1[:3] + b1
    __shared__ float sw2[NH];
    __shared__ float snrm[3];
    if (l < NH) {
        float px = points[3 * n + 0], py = points[3 * n + 1], pz = points[3 * n + 2];
        spb[l] = fmaf(px, W1[l], fmaf(py, W1[NH + l], fmaf(pz, W1[2 * NH + l], b1[l])));
        sw2[l] = W2[l];
    }
    if (l >= 32 && l < 35) snrm[l - 32] = normals[3 * n + (l - 32)];
    __syncthreads();

    float nx = snrm[0], ny = snrm[1], nz = snrm[2];
    float nU = fmaf(gSU[l], nx, fmaf(gSU[NL + l], ny, gSU[2 * NL + l] * nz));
    float nV = fmaf(gSV[l], nx, fmaf(gSV[NL + l], ny, gSV[2 * NL + l] * nz));
    float nC = fmaf(gCL[l], nx, fmaf(gCL[NL + l], ny, gCL[2 * NL + l] * nz));
    float bb2 = b2[0];

    const float4* rp = (const float4*)(rthr + (((size_t)n * NL + l) * NS));
    float4 ra = rp[0], rb = rp[1];
    float rr[NS] = {ra.x, ra.y, ra.z, ra.w, rb.x, rb.y, rb.z, rb.w};

    // theta_s = (pi/4)*(r_s + s): poly on (pi/4)*r_s, then exact rotation by s*pi/4
    const float H = 0.70710678118654752f;
    float st[NS], ct[NS], acc[NS];
    #pragma unroll
    for (int s = 0; s < NS; s++) {
        float sp, cp;
        sincos_q(rr[s], sp, cp);
        float sum = cp + sp, dif = cp - sp;
        float stv, ctv;
        if      (s == 0) { stv =  sp;      ctv =  cp;      }
        else if (s == 1) { stv =  H * sum; ctv =  H * dif; }
        else if (s == 2) { stv =  cp;      ctv = -sp;      }
        else if (s == 3) { stv =  H * dif; ctv = -H * sum; }
        else if (s == 4) { stv = -sp;      ctv = -cp;      }
        else if (s == 5) { stv = -H * sum; ctv = -H * dif; }
        else if (s == 6) { stv = -cp;      ctv =  sp;      }
        else             { stv = -H * dif; ctv =  H * sum; }
        st[s] = stv; ct[s] = ctv;
        acc[s] = bb2;
    }

    // j outer (stream tables, coalesced), s inner (8 accumulators)
    #pragma unroll
    for (int j = 0; j < NH; j++) {
        float Aj  = gA [j * NL + l];
        float Bj  = gB [j * NL + l];
        float Cj  = gC0[j * NL + l] + spb[j];
        float w2j = sw2[j];
        #pragma unroll
        for (int s = 0; s < NS; s++) {
            float h = fmaf(-ct[s], Aj, fmaf(-st[s], Bj, Cj));
            h = fmaxf(h, 0.0f);
            acc[s] = fmaf(h, w2j, acc[s]);
        }
    }

    float vsum = 0.0f;
    #pragma unroll
    for (int s = 0; s < NS; s++) {
        float pred = __fdividef(1.0f, 1.0f + __expf(-acc[s]));
        float cd = fmaf(ct[s], nU, fmaf(st[s], nV, nC));
        vsum += (cd > 1e-6f) ? pred : 0.0f;
    }

    float w = gWt[l];
    out[(size_t)n * NL + l] = w * vsum / (8.0f * w + 1e-6f);
}

extern "C" void kernel_launch(void* const* d_in, const int* in_sizes, int n_in,
                              void* d_out, int out_size)
{
    const float* points   = (const float*)d_in[0];
    const float* normals  = (const float*)d_in[1];
    const float* root_rot = (const float*)d_in[2];
    const float* lobes    = (const float*)d_in[3];
    const float* lambdas  = (const float*)d_in[4];
    const float* rthr     = (const float*)d_in[5];
    const float* W1       = (const float*)d_in[6];
    const float* b1       = (const float*)d_in[7];
    const float* W2       = (const float*)d_in[8];
    const float* b2       = (const float*)d_in[9];
    float* out = (float*)d_out;

    int N = in_sizes[0] / 3;

    setup_kernel<<<1, NL>>>(root_rot, lobes, lambdas, W1);
    main_kernel<<<N, NL>>>(points, normals, rthr, W1, b1, W2, b2, out);
}

// round 5
// speedup vs baseline: 3.0827x; 1.1626x over previous
#include <cuda_runtime.h>
#include <math.h>

#define NL 128   // L lobes
#define NS 8     // samples per lobe
#define NH 16    // hidden units

// Fused per-(j,l) table: {A, B, C0, w2}, lane-major in l for coalesced LDG.128
//   A  = sp * (U . M_j)
//   B  = sp * (V . M_j)
//   C0 = -cp * (l . M_j)
//   w2 = W2[j]
__device__ float4 gT [NH * NL];
__device__ float  gSU[3 * NL];   // sp * U   -> gSU[d*NL + l]
__device__ float  gSV[3 * NL];   // sp * V
__device__ float  gCL[3 * NL];   // cp * l
__device__ float  gWt[NL];       // exp(sharp * (cp*|l|^2 - 1))

__global__ void setup_kernel(const float* __restrict__ root_rot,
                             const float* __restrict__ lobes,
                             const float* __restrict__ lambdas,
                             const float* __restrict__ W1,
                             const float* __restrict__ W2)
{
    __shared__ float sM[3 * NH];   // M = R @ W1[3:6]  (M[d][j])
    int t = threadIdx.x;
    if (t < 3 * NH) {
        int d = t >> 4, j = t & 15;
        sM[t] = root_rot[d * 3 + 0] * W1[(3 + 0) * NH + j]
              + root_rot[d * 3 + 1] * W1[(3 + 1) * NH + j]
              + root_rot[d * 3 + 2] * W1[(3 + 2) * NH + j];
    }
    __syncthreads();

    int l = t;  // 128 threads, one per lobe
    float lx = lobes[3 * l + 0], ly = lobes[3 * l + 1], lz = lobes[3 * l + 2];
    float inv = 1.0f / (sqrtf(lx * lx + ly * ly + lz * lz) + 1e-6f);
    lx *= inv; ly *= inv; lz *= inv;

    // U = normalize(cross(z, l)) = normalize((-ly, lx, 0))
    float ux = -ly, uy = lx, uz = 0.0f;
    float un = 1.0f / (sqrtf(ux * ux + uy * uy) + 1e-6f);
    ux *= un; uy *= un;

    // V = normalize(cross(l, U))
    float vx = ly * uz - lz * uy;
    float vy = lz * ux - lx * uz;
    float vz = lx * uy - ly * ux;
    float vn = 1.0f / (sqrtf(vx * vx + vy * vy + vz * vz) + 1e-6f);
    vx *= vn; vy *= vn; vz *= vn;

    float sharp = lambdas[l];
    float rphi = acosf(1.0f - 1.0f / sharp);
    rphi = fminf(rphi, 1.0471975511965976f);  // pi/3
    float sp = sinf(rphi), cp = cosf(rphi);

    #pragma unroll
    for (int j = 0; j < NH; j++) {
        float mx = sM[j], my = sM[NH + j], mz = sM[2 * NH + j];
        float A  = sp * (ux * mx + uy * my + uz * mz);
        float B  = sp * (vx * mx + vy * my + vz * mz);
        float C0 = -cp * (lx * mx + ly * my + lz * mz);
        gT[j * NL + l] = make_float4(A, B, C0, W2[j]);
    }
    gSU[0 * NL + l] = sp * ux; gSU[1 * NL + l] = sp * uy; gSU[2 * NL + l] = sp * uz;
    gSV[0 * NL + l] = sp * vx; gSV[1 * NL + l] = sp * vy; gSV[2 * NL + l] = sp * vz;
    gCL[0 * NL + l] = cp * lx; gCL[1 * NL + l] = cp * ly; gCL[2 * NL + l] = cp * lz;

    float ll2 = lx * lx + ly * ly + lz * lz;
    gWt[l] = __expf(sharp * (cp * ll2 - 1.0f));
}

// ---- packed f32x2 helpers (FFMA2 only reachable via PTX) ----
typedef unsigned long long u64;

__device__ __forceinline__ u64 pack2(float lo, float hi) {
    u64 r; asm("mov.b64 %0, {%1, %2};" : "=l"(r) : "f"(lo), "f"(hi)); return r;
}
__device__ __forceinline__ void unpack2(u64 v, float& lo, float& hi) {
    asm("mov.b64 {%0, %1}, %2;" : "=f"(lo), "=f"(hi) : "l"(v));
}
__device__ __forceinline__ u64 fma2(u64 a, u64 b, u64 c) {
    u64 d; asm("fma.rn.f32x2 %0, %1, %2, %3;" : "=l"(d) : "l"(a), "l"(b), "l"(c)); return d;
}

// sin/cos of phi = (pi/4)*r for r in [0,1) — minimax, no range reduction.
__device__ __forceinline__ void sincos_q(float r, float& sp, float& cp)
{
    float phi = 0.7853981633974483f * r;
    float x2  = phi * phi;
    float ps = fmaf(x2, -1.9515295891e-4f, 8.3321608736e-3f);
    ps       = fmaf(x2, ps, -1.6666654611e-1f);
    sp       = fmaf(phi * x2, ps, phi);
    float pc = fmaf(x2, 2.443315711809948e-5f, -1.388731625493765e-3f);
    pc       = fmaf(x2, pc, 4.166664568298827e-2f);
    pc       = fmaf(x2, pc, -0.5f);
    cp       = fmaf(x2, pc, 1.0f);
}

__global__ __launch_bounds__(NL) void main_kernel(
    const float* __restrict__ points,
    const float* __restrict__ normals,
    const float* __restrict__ rthr,
    const float* __restrict__ W1,
    const float* __restrict__ b1,
    const float* __restrict__ b2,
    float* __restrict__ out)
{
    int n = blockIdx.x;
    int l = threadIdx.x;

    __shared__ float spb[NH];   // per-point bias: p @ W1[:3] + b1
    __shared__ float snrm[3];
    if (l < NH) {
        float px = points[3 * n + 0], py = points[3 * n + 1], pz = points[3 * n + 2];
        spb[l] = fmaf(px, W1[l], fmaf(py, W1[NH + l], fmaf(pz, W1[2 * NH + l], b1[l])));
    }
    if (l >= 32 && l < 35) snrm[l - 32] = normals[3 * n + (l - 32)];
    __syncthreads();

    float nx = snrm[0], ny = snrm[1], nz = snrm[2];
    float nU = fmaf(gSU[l], nx, fmaf(gSU[NL + l], ny, gSU[2 * NL + l] * nz));
    float nV = fmaf(gSV[l], nx, fmaf(gSV[NL + l], ny, gSV[2 * NL + l] * nz));
    float nC = fmaf(gCL[l], nx, fmaf(gCL[NL + l], ny, gCL[2 * NL + l] * nz));
    float bb2 = b2[0];

    const float4* rp = (const float4*)(rthr + (((size_t)n * NL + l) * NS));
    float4 ra = rp[0], rb = rp[1];
    float rr[NS] = {ra.x, ra.y, ra.z, ra.w, rb.x, rb.y, rb.z, rb.w};

    // theta_s = (pi/4)*(r_s + s): poly on (pi/4)*r_s, then exact rotation by s*pi/4.
    // Produce NEGATED sin/cos directly (sign flip free in the rotation table).
    const float H = 0.70710678118654752f;
    float nst[NS], nct[NS];
    #pragma unroll
    for (int s = 0; s < NS; s++) {
        float sp, cp;
        sincos_q(rr[s], sp, cp);
        float sum = cp + sp, dif = cp - sp;
        float nstv, nctv;
        if      (s == 0) { nstv = -sp;      nctv = -cp;      }
        else if (s == 1) { nstv = -H * sum; nctv = -H * dif; }
        else if (s == 2) { nstv = -cp;      nctv =  sp;      }
        else if (s == 3) { nstv = -H * dif; nctv =  H * sum; }
        else if (s == 4) { nstv =  sp;      nctv =  cp;      }
        else if (s == 5) { nstv =  H * sum; nctv =  H * dif; }
        else if (s == 6) { nstv =  cp;      nctv = -sp;      }
        else             { nstv =  H * dif; nctv = -H * sum; }
        nst[s] = nstv; nct[s] = nctv;
    }

    // Pack sample pairs for f32x2
    u64 nst2[4], nct2[4], acc2[4];
    u64 bb22 = pack2(bb2, bb2);
    #pragma unroll
    for (int p = 0; p < 4; p++) {
        nst2[p] = pack2(nst[2 * p], nst[2 * p + 1]);
        nct2[p] = pack2(nct[2 * p], nct[2 * p + 1]);
        acc2[p] = bb22;
    }

    // j outer (stream fused table, 1 LDG.128/j), s-pairs inner (4 packed accumulators)
    const float4* T = gT + l;
    #pragma unroll
    for (int j = 0; j < NH; j++) {
        float4 t = T[j * NL];
        float Cj = t.z + spb[j];
        u64 A2 = pack2(t.x, t.x);
        u64 B2 = pack2(t.y, t.y);
        u64 C2 = pack2(Cj, Cj);
        u64 W2p = pack2(t.w, t.w);
        #pragma unroll
        for (int p = 0; p < 4; p++) {
            u64 h2 = fma2(nct2[p], A2, fma2(nst2[p], B2, C2));
            float h0, h1;
            unpack2(h2, h0, h1);
            h0 = fmaxf(h0, 0.0f);
            h1 = fmaxf(h1, 0.0f);
            acc2[p] = fma2(pack2(h0, h1), W2p, acc2[p]);
        }
    }

    float vsum = 0.0f;
    #pragma unroll
    for (int p = 0; p < 4; p++) {
        float a0, a1;
        unpack2(acc2[p], a0, a1);
        float pred0 = __fdividef(1.0f, 1.0f + __expf(-a0));
        float pred1 = __fdividef(1.0f, 1.0f + __expf(-a1));
        float cd0 = fmaf(-nct[2 * p],     nU, fmaf(-nst[2 * p],     nV, nC));
        float cd1 = fmaf(-nct[2 * p + 1], nU, fmaf(-nst[2 * p + 1], nV, nC));
        vsum += (cd0 > 1e-6f) ? pred0 : 0.0f;
        vsum += (cd1 > 1e-6f) ? pred1 : 0.0f;
    }

    float w = gWt[l];
    out[(size_t)n * NL + l] = w * vsum / (8.0f * w + 1e-6f);
}

extern "C" void kernel_launch(void* const* d_in, const int* in_sizes, int n_in,
                              void* d_out, int out_size)
{
    const float* points   = (const float*)d_in[0];
    const float* normals  = (const float*)d_in[1];
    const float* root_rot = (const float*)d_in[2];
    const float* lobes    = (const float*)d_in[3];
    const float* lambdas  = (const float*)d_in[4];
    const float* rthr     = (const float*)d_in[5];
    const float* W1       = (const float*)d_in[6];
    const float* b1       = (const float*)d_in[7];
    const float* W2       = (const float*)d_in[8];
    const float* b2       = (const float*)d_in[9];
    float* out = (float*)d_out;

    int N = in_sizes[0] / 3;

    setup_kernel<<<1, NL>>>(root_rot, lobes, lambdas, W1, W2);
    main_kernel<<<N, NL>>>(points, normals, rthr, W1, b1, b2, out);
}